// round 5
// baseline (speedup 1.0000x reference)
#include <cuda_runtime.h>
#include <cstdint>

// Problem shape (fixed by reference)
static constexpr int B_ = 8, M_ = 4096, N_ = 1024, D_ = 1024;
static constexpr int ROWS = B_ * M_;           // 32768 flattened LN rows
static constexpr int TM = 128;                 // CTA M tile
static constexpr int TN = 128;                 // CTA D tile
static constexpr int KC = 32;                  // K per chunk
static constexpr int NCHUNK = N_ / KC;         // 32

// Fragment-layout SMEM: A blocks (mt 0..7, ks 0..3), 128 payload words + 4 pad
static constexpr int A_BLK_STRIDE = 132;       // words; keeps 16B alignment for v4
static constexpr int A_STAGE_WORDS = 32 * A_BLK_STRIDE;   // 4224
// B blocks (ntile 0..15, ks 0..3), 64 payload words + 2 pad
static constexpr int B_BLK_STRIDE = 66;        // words; keeps 8B alignment for v2
static constexpr int B_STAGE_WORDS = 64 * B_BLK_STRIDE;   // 4224
static constexpr int STAGE_WORDS = A_STAGE_WORDS + B_STAGE_WORDS;  // 8448
static constexpr int SMEM_WORDS = 2 * STAGE_WORDS;                  // 16896
static constexpr int SMEM_DYN = SMEM_WORDS * 4;                     // 67584 B

// Row LN statistics (device-global scratch; no allocation)
__device__ float g_mean[ROWS];
__device__ float g_rstd[ROWS];

__device__ __forceinline__ uint32_t f2tf32(float f) {
    uint32_t r;
    asm("cvt.rna.tf32.f32 %0, %1;" : "=r"(r) : "f"(f));
    return r;
}

__device__ __forceinline__ void mma_tf32(float* c, const uint32_t* a, const uint32_t* b) {
    asm volatile(
        "mma.sync.aligned.m16n8k8.row.col.f32.tf32.tf32.f32 "
        "{%0,%1,%2,%3}, {%4,%5,%6,%7}, {%8,%9}, {%0,%1,%2,%3};"
        : "+f"(c[0]), "+f"(c[1]), "+f"(c[2]), "+f"(c[3])
        : "r"(a[0]), "r"(a[1]), "r"(a[2]), "r"(a[3]), "r"(b[0]), "r"(b[1]));
}

// --------------------------------------------------------- LN stats kernel ---
__global__ void __launch_bounds__(256) ln_stats_kernel(const float* __restrict__ x) {
    const int row = blockIdx.x;
    float4 v = reinterpret_cast<const float4*>(x + (size_t)row * N_)[threadIdx.x];
    float s  = v.x + v.y + v.z + v.w;
    float ss = v.x * v.x + v.y * v.y + v.z * v.z + v.w * v.w;
#pragma unroll
    for (int o = 16; o > 0; o >>= 1) {
        s  += __shfl_xor_sync(0xffffffffu, s, o);
        ss += __shfl_xor_sync(0xffffffffu, ss, o);
    }
    __shared__ float sh[16];
    const int wid = threadIdx.x >> 5, lid = threadIdx.x & 31;
    if (lid == 0) { sh[wid] = s; sh[8 + wid] = ss; }
    __syncthreads();
    if (threadIdx.x == 0) {
        float ts = 0.f, tss = 0.f;
#pragma unroll
        for (int i = 0; i < 8; i++) { ts += sh[i]; tss += sh[8 + i]; }
        const float m   = ts * (1.0f / N_);
        const float var = tss * (1.0f / N_) - m * m;
        g_mean[row] = m;
        g_rstd[row] = rsqrtf(var + 1e-5f);
    }
}

// ---------------------------------------------------- fused LN+GEMM kernel ---
// Fragment-layout SMEM word addressing (matches PTX m16n8k8 tf32 fragments):
//  A value (m 0..127, k 0..31):
//    word = (mt*4 + ks)*132 + ((m&7)*4 + (k&3))*4 + (((m>>3)&1) + 2*((k>>2)&1))
//  B value (k 0..31, n 0..127):
//    word = (nt*4 + ks)*66  + ((n&7)*4 + (k&3))*2 + ((k>>2)&1)
__global__ void __launch_bounds__(256) ln_gemm_kernel(
    const float* __restrict__ x, const float* __restrict__ w, const float* __restrict__ bias,
    const float* __restrict__ gamma, const float* __restrict__ beta, float* __restrict__ out) {
    extern __shared__ uint32_t smw[];
    uint32_t* Abuf[2] = { smw, smw + STAGE_WORDS };
    uint32_t* Bbuf[2] = { smw + A_STAGE_WORDS, smw + STAGE_WORDS + A_STAGE_WORDS };

    const int tid = threadIdx.x;
    const int wid = tid >> 5, lane = tid & 31;
    const int d0 = blockIdx.x * TN;
    const int row_base = blockIdx.y * TM;

    // ---- staging maps
    // A: thread handles rows m = arow + 32*jj (jj 0..3), k = af4*4 .. +3
    const int arow = tid >> 3;
    const int af4  = tid & 7;
    // B: warp wid covers n in [bnb, bnb+32), k offset bk0 (+8*jj); lane spreads (n,k)
    const int bnb = (wid & 3) * 32;
    const int bk0 = (wid >> 2) * 4;
    const int bln = lane >> 2;   // n sub-offset 0..7
    const int blt = lane & 3;    // k sub-offset 0..3

    // Preload LN stats for this thread's 4 rows
    float amean[4], arstd[4];
#pragma unroll
    for (int jj = 0; jj < 4; jj++) {
        amean[jj] = g_mean[row_base + arow + 32 * jj];
        arstd[jj] = g_rstd[row_base + arow + 32 * jj];
    }

    // Accumulators: warp tile 64(M) x 32(N) -> 4 mtiles x 4 ntiles x 4 regs
    const int wm = wid >> 2;   // 0..1
    const int wn = wid & 3;    // 0..3
    float acc[4][4][4];
#pragma unroll
    for (int i = 0; i < 4; i++)
#pragma unroll
        for (int j = 0; j < 4; j++)
#pragma unroll
            for (int r = 0; r < 4; r++) acc[i][j][r] = 0.f;

    // ---- prefetch chunk 0
    float4 pax[4];
    float  pb[16];
    float4 pg, pbt;
    {
        const int cc = 0;
        pg  = *reinterpret_cast<const float4*>(gamma + cc * KC + af4 * 4);
        pbt = *reinterpret_cast<const float4*>(beta  + cc * KC + af4 * 4);
#pragma unroll
        for (int jj = 0; jj < 4; jj++)
            pax[jj] = *reinterpret_cast<const float4*>(
                x + (size_t)(row_base + arow + 32 * jj) * N_ + cc * KC + af4 * 4);
#pragma unroll
        for (int jj = 0; jj < 4; jj++)
#pragma unroll
            for (int ii = 0; ii < 4; ii++)
                pb[jj * 4 + ii] = w[(size_t)(cc * KC + bk0 + 8 * jj + blt) * D_
                                    + d0 + bnb + bln + 8 * ii];
    }

    for (int c = 0; c < NCHUNK; c++) {
        const int s = c & 1;
        uint32_t* As = Abuf[s];
        uint32_t* Bs = Bbuf[s];

        // ---- STS A (apply LN + tf32 convert)
#pragma unroll
        for (int jj = 0; jj < 4; jj++) {
            const int m = arow + 32 * jj;
            const int mt = m >> 4;
            const int g = m & 7;
            const int hi = (m >> 3) & 1;
            const float mn = amean[jj], rs = arstd[jj];
            const float4 v = pax[jj];
            const float lv[4] = {
                (v.x - mn) * rs * pg.x + pbt.x,
                (v.y - mn) * rs * pg.y + pbt.y,
                (v.z - mn) * rs * pg.z + pbt.z,
                (v.w - mn) * rs * pg.w + pbt.w };
#pragma unroll
            for (int e = 0; e < 4; e++) {
                const int k = af4 * 4 + e;
                const int word = (mt * 4 + (k >> 3)) * A_BLK_STRIDE
                               + (g * 4 + (k & 3)) * 4 + (hi + 2 * ((k >> 2) & 1));
                As[word] = f2tf32(lv[e]);
            }
        }
        // ---- STS B (tf32 convert)
#pragma unroll
        for (int jj = 0; jj < 4; jj++)
#pragma unroll
            for (int ii = 0; ii < 4; ii++) {
                const int k = bk0 + 8 * jj + blt;
                const int n = bnb + bln + 8 * ii;
                const int word = ((n >> 3) * 4 + (k >> 3)) * B_BLK_STRIDE
                               + ((n & 7) * 4 + (k & 3)) * 2 + ((k >> 2) & 1);
                Bs[word] = f2tf32(pb[jj * 4 + ii]);
            }

        __syncthreads();

        // ---- prefetch next chunk (overlap LDG latency with MMA below)
        if (c + 1 < NCHUNK) {
            const int cc = c + 1;
            pg  = *reinterpret_cast<const float4*>(gamma + cc * KC + af4 * 4);
            pbt = *reinterpret_cast<const float4*>(beta  + cc * KC + af4 * 4);
#pragma unroll
            for (int jj = 0; jj < 4; jj++)
                pax[jj] = *reinterpret_cast<const float4*>(
                    x + (size_t)(row_base + arow + 32 * jj) * N_ + cc * KC + af4 * 4);
#pragma unroll
            for (int jj = 0; jj < 4; jj++)
#pragma unroll
                for (int ii = 0; ii < 4; ii++)
                    pb[jj * 4 + ii] = w[(size_t)(cc * KC + bk0 + 8 * jj + blt) * D_
                                        + d0 + bnb + bln + 8 * ii];
        }

        // ---- MMA over this chunk
#pragma unroll
        for (int ks = 0; ks < 4; ks++) {
            uint32_t afr[4][4];
#pragma unroll
            for (int i = 0; i < 4; i++) {
                const uint4 va = *reinterpret_cast<const uint4*>(
                    &As[((wm * 4 + i) * 4 + ks) * A_BLK_STRIDE + lane * 4]);
                afr[i][0] = va.x; afr[i][1] = va.y; afr[i][2] = va.z; afr[i][3] = va.w;
            }
            uint32_t bfr[4][2];
#pragma unroll
            for (int j = 0; j < 4; j++) {
                const uint2 vb = *reinterpret_cast<const uint2*>(
                    &Bs[((wn * 4 + j) * 4 + ks) * B_BLK_STRIDE + lane * 2]);
                bfr[j][0] = vb.x; bfr[j][1] = vb.y;
            }
#pragma unroll
            for (int i = 0; i < 4; i++)
#pragma unroll
                for (int j = 0; j < 4; j++)
                    mma_tf32(acc[i][j], afr[i], bfr[j]);
        }
        // one sync per iter: next iter's STS targets the other buffer; writes to
        // THIS buffer happen only after everyone passed next iter's sync.
    }

    // ---- epilogue: acc + bias -> gmem
    const int g = lane >> 2;         // fragment row group 0..7
    const int t = lane & 3;          // fragment col pair 0..3
    float2 bb[4];
#pragma unroll
    for (int j = 0; j < 4; j++) {
        const int col = d0 + wn * 32 + j * 8 + 2 * t;
        bb[j] = *reinterpret_cast<const float2*>(bias + col);
    }
#pragma unroll
    for (int i = 0; i < 4; i++) {
        const int r0 = row_base + wm * 64 + i * 16 + g;
#pragma unroll
        for (int j = 0; j < 4; j++) {
            const int col = d0 + wn * 32 + j * 8 + 2 * t;
            float2 o0, o1;
            o0.x = acc[i][j][0] + bb[j].x;
            o0.y = acc[i][j][1] + bb[j].y;
            o1.x = acc[i][j][2] + bb[j].x;
            o1.y = acc[i][j][3] + bb[j].y;
            *reinterpret_cast<float2*>(out + (size_t)r0 * D_ + col) = o0;
            *reinterpret_cast<float2*>(out + (size_t)(r0 + 8) * D_ + col) = o1;
        }
    }
}

// ------------------------------------------------------------------ launch ---
extern "C" void kernel_launch(void* const* d_in, const int* in_sizes, int n_in,
                              void* d_out, int out_size) {
    const float* x     = (const float*)d_in[0];
    const float* w     = (const float*)d_in[1];
    const float* b     = (const float*)d_in[2];
    const float* gamma = (const float*)d_in[3];
    const float* beta  = (const float*)d_in[4];
    float* out = (float*)d_out;

    cudaFuncSetAttribute(ln_gemm_kernel, cudaFuncAttributeMaxDynamicSharedMemorySize, SMEM_DYN);

    ln_stats_kernel<<<ROWS, 256>>>(x);
    ln_gemm_kernel<<<dim3(D_ / TN, ROWS / TM), 256, SMEM_DYN>>>(x, w, b, gamma, beta, out);
}

// round 7
// speedup vs baseline: 2.1852x; 2.1852x over previous
#include <cuda_runtime.h>
#include <cstdint>

// Problem shape (fixed by reference)
static constexpr int B_ = 8, M_ = 4096, N_ = 1024, D_ = 1024;
static constexpr int ROWS = B_ * M_;            // 32768 LN rows
static constexpr int TM = 128, TN = 128;        // CTA tile
static constexpr int KC = 32;                   // K per chunk
static constexpr int NCHUNK = N_ / KC;          // 32
static constexpr int RB = ROWS / TM;            // 256 row blocks
static constexpr int NB = D_ / TN;              // 8 col blocks

// SMEM: 3 stages x (A 4096 words + B 4096 words)
static constexpr int A_CHUNK_WORDS = TM * KC;   // 4096
static constexpr int B_CHUNK_WORDS = KC * TN;   // 4096
static constexpr int STAGE_WORDS = A_CHUNK_WORDS + B_CHUNK_WORDS;  // 8192
static constexpr int NSTAGE = 3;
static constexpr int SMEM_DYN = NSTAGE * STAGE_WORDS * 4;          // 98304 B

// Device-global scratch (no allocation APIs)
__device__ float g_mean[ROWS];
__device__ float g_rstd[ROWS];
// A fragments: [rb 256][c 32][mt 8][ks 4][lane 32][reg 4]  (tf32 words)
__device__ uint32_t g_afrag[(size_t)RB * NCHUNK * A_CHUNK_WORDS];
// B fragments: [nb 8][c 32][nt 16][ks 4][lane 32][reg 2]
__device__ uint32_t g_bfrag[(size_t)NB * NCHUNK * B_CHUNK_WORDS];

// ---------------------------------------------------------------- helpers ---
__device__ __forceinline__ uint32_t f2tf32(float f) {
    uint32_t r;
    asm("cvt.rna.tf32.f32 %0, %1;" : "=r"(r) : "f"(f));
    return r;
}

__device__ __forceinline__ uint32_t smem_u32(const void* p) {
    uint32_t a;
    asm("{ .reg .u64 t; cvta.to.shared.u64 t, %1; cvt.u32.u64 %0, t; }" : "=r"(a) : "l"(p));
    return a;
}

__device__ __forceinline__ void mma_tf32(float* c, const uint32_t* a, const uint32_t* b) {
    asm volatile(
        "mma.sync.aligned.m16n8k8.row.col.f32.tf32.tf32.f32 "
        "{%0,%1,%2,%3}, {%4,%5,%6,%7}, {%8,%9}, {%0,%1,%2,%3};"
        : "+f"(c[0]), "+f"(c[1]), "+f"(c[2]), "+f"(c[3])
        : "r"(a[0]), "r"(a[1]), "r"(a[2]), "r"(a[3]), "r"(b[0]), "r"(b[1]));
}

__device__ __forceinline__ void cpasync16(uint32_t smem_addr, const void* gptr) {
    asm volatile("cp.async.cg.shared.global [%0], [%1], 16;"
                 :: "r"(smem_addr), "l"(gptr) : "memory");
}
#define CP_COMMIT()  asm volatile("cp.async.commit_group;" ::: "memory")
#define CP_WAIT(n)   asm volatile("cp.async.wait_group %0;" :: "n"(n) : "memory")

#define LDS128(r0, r1, r2, r3, addr) \
    asm volatile("ld.shared.v4.b32 {%0,%1,%2,%3}, [%4];" \
                 : "=r"(r0), "=r"(r1), "=r"(r2), "=r"(r3) : "r"(addr))
#define LDS64(r0, r1, addr) \
    asm volatile("ld.shared.v2.b32 {%0,%1}, [%2];" : "=r"(r0), "=r"(r1) : "r"(addr))

// --------------------------------------------------------- LN stats kernel ---
__global__ void __launch_bounds__(256) ln_stats_kernel(const float* __restrict__ x) {
    const int row = blockIdx.x;
    float4 v = reinterpret_cast<const float4*>(x + (size_t)row * N_)[threadIdx.x];
    float s  = v.x + v.y + v.z + v.w;
    float ss = v.x * v.x + v.y * v.y + v.z * v.z + v.w * v.w;
#pragma unroll
    for (int o = 16; o > 0; o >>= 1) {
        s  += __shfl_xor_sync(0xffffffffu, s, o);
        ss += __shfl_xor_sync(0xffffffffu, ss, o);
    }
    __shared__ float sh[16];
    const int wid = threadIdx.x >> 5, lid = threadIdx.x & 31;
    if (lid == 0) { sh[wid] = s; sh[8 + wid] = ss; }
    __syncthreads();
    if (threadIdx.x == 0) {
        float ts = 0.f, tss = 0.f;
#pragma unroll
        for (int i = 0; i < 8; i++) { ts += sh[i]; tss += sh[8 + i]; }
        const float m   = ts * (1.0f / N_);
        const float var = tss * (1.0f / N_) - m * m;
        g_mean[row] = m;
        g_rstd[row] = rsqrtf(var + 1e-5f);
    }
}

// ------------------------------------------- LN -> tf32 A-fragment kernel ---
// Fragment mapping (verified on HW by the R5 passing kernel):
//   reg0 = (row g,   k t)   reg1 = (row g+8, k t)
//   reg2 = (row g,   k t+4) reg3 = (row g+8, k t+4)   g=lane>>2, t=lane&3
__global__ void __launch_bounds__(256) ln_frag_kernel(
    const float* __restrict__ x, const float* __restrict__ gamma,
    const float* __restrict__ beta) {
    const int c = blockIdx.x, rb = blockIdx.y;
    const int tid = threadIdx.x, mt = tid >> 5, lane = tid & 31;
    const int g = lane >> 2, t = lane & 3;
    const int m0 = rb * TM + mt * 16 + g, m1 = m0 + 8;
    const float mn0 = g_mean[m0], rs0 = g_rstd[m0];
    const float mn1 = g_mean[m1], rs1 = g_rstd[m1];
    const float* x0 = x + (size_t)m0 * N_ + c * KC;
    const float* x1 = x + (size_t)m1 * N_ + c * KC;
    uint32_t* dst = g_afrag + ((size_t)(rb * NCHUNK + c) * 32 + mt * 4) * 128 + lane * 4;
#pragma unroll
    for (int ks = 0; ks < 4; ks++) {
        const int k0 = ks * 8 + t, k1 = k0 + 4;
        const float ga0 = gamma[c * KC + k0], be0 = beta[c * KC + k0];
        const float ga1 = gamma[c * KC + k1], be1 = beta[c * KC + k1];
        uint4 o;
        o.x = f2tf32((x0[k0] - mn0) * rs0 * ga0 + be0);
        o.y = f2tf32((x1[k0] - mn1) * rs1 * ga0 + be0);
        o.z = f2tf32((x0[k1] - mn0) * rs0 * ga1 + be1);
        o.w = f2tf32((x1[k1] - mn1) * rs1 * ga1 + be1);
        *reinterpret_cast<uint4*>(dst + ks * 128) = o;
    }
}

// --------------------------------------------- w -> tf32 B-fragment kernel ---
//   reg0 = (k t, n g)   reg1 = (k t+4, n g)
__global__ void __launch_bounds__(256) w_frag_kernel(const float* __restrict__ w) {
    const int c = blockIdx.x, nb = blockIdx.y;
    const int tid = threadIdx.x, lane = tid & 31;
    const int ks = (tid >> 5) & 3, half = tid >> 7;
    const int g = lane >> 2, t = lane & 3;
    const int k0 = c * KC + ks * 8 + t;
#pragma unroll
    for (int h = 0; h < 8; h++) {
        const int nt = half * 8 + h;
        const int n = nb * TN + nt * 8 + g;
        uint2 o;
        o.x = f2tf32(w[(size_t)k0 * D_ + n]);
        o.y = f2tf32(w[(size_t)(k0 + 4) * D_ + n]);
        *reinterpret_cast<uint2*>(
            g_bfrag + ((size_t)(nb * NCHUNK + c) * 16 + nt) * 256 + ks * 64 + lane * 2) = o;
    }
}

// ------------------------------------------------------------- GEMM kernel ---
__global__ void __launch_bounds__(256, 2) ln_gemm_kernel(
    const float* __restrict__ bias, float* __restrict__ out) {
    extern __shared__ uint32_t smw[];
    const uint32_t sbase = smem_u32(smw);
    const int tid = threadIdx.x, wid = tid >> 5, lane = tid & 31;
    const int bx = blockIdx.x, by = blockIdx.y;
    const int wm = wid >> 2, wn = wid & 3;

    const uint4* gA = reinterpret_cast<const uint4*>(g_afrag) + (size_t)by * NCHUNK * 1024;
    const uint4* gB = reinterpret_cast<const uint4*>(g_bfrag) + (size_t)bx * NCHUNK * 1024;

    // issue one chunk's copies into a stage (8 x 16B per thread) + commit
    auto issue = [&](int chunk, int stage) {
        const uint32_t dstA = sbase + (uint32_t)stage * (STAGE_WORDS * 4) + tid * 16;
        const uint4* srcA = gA + chunk * 1024 + tid;
#pragma unroll
        for (int i = 0; i < 4; i++) cpasync16(dstA + i * 4096, srcA + i * 256);
        const uint32_t dstB = dstA + A_CHUNK_WORDS * 4;
        const uint4* srcB = gB + chunk * 1024 + tid;
#pragma unroll
        for (int i = 0; i < 4; i++) cpasync16(dstB + i * 4096, srcB + i * 256);
        CP_COMMIT();
    };

    issue(0, 0);
    issue(1, 1);

    float acc[4][4][4];
#pragma unroll
    for (int i = 0; i < 4; i++)
#pragma unroll
        for (int j = 0; j < 4; j++)
#pragma unroll
            for (int r = 0; r < 4; r++) acc[i][j][r] = 0.f;

    for (int c = 0; c < NCHUNK; c++) {
        // chunk c complete when <=1 (or 0 at the tail) groups remain in flight
        if (c < NCHUNK - 2) { CP_WAIT(1); } else { CP_WAIT(0); }
        __syncthreads();   // also guarantees everyone finished reading stage (c-1)%3
        if (c + 2 < NCHUNK) issue(c + 2, (c + 2) % NSTAGE);

        const uint32_t Asw = sbase + (uint32_t)(c % NSTAGE) * (STAGE_WORDS * 4);
        const uint32_t Bsw = Asw + A_CHUNK_WORDS * 4;

#pragma unroll
        for (int ks = 0; ks < 4; ks++) {
            uint32_t afr[4][4];
#pragma unroll
            for (int i = 0; i < 4; i++)
                LDS128(afr[i][0], afr[i][1], afr[i][2], afr[i][3],
                       Asw + (uint32_t)(((wm * 4 + i) * 4 + ks) * 512 + lane * 16));
            uint32_t bfr[4][2];
#pragma unroll
            for (int j = 0; j < 4; j++)
                LDS64(bfr[j][0], bfr[j][1],
                      Bsw + (uint32_t)(((wn * 4 + j) * 4 + ks) * 256 + lane * 8));
#pragma unroll
            for (int i = 0; i < 4; i++)
#pragma unroll
                for (int j = 0; j < 4; j++)
                    mma_tf32(acc[i][j], afr[i], bfr[j]);
        }
    }

    // ---- epilogue: acc + bias -> gmem (layout identical to R5 passing kernel)
    const int d0 = bx * TN;
    const int row_base = by * TM;
    const int g = lane >> 2;
    const int t = lane & 3;
    float2 bb[4];
#pragma unroll
    for (int j = 0; j < 4; j++)
        bb[j] = *reinterpret_cast<const float2*>(bias + d0 + wn * 32 + j * 8 + 2 * t);
#pragma unroll
    for (int i = 0; i < 4; i++) {
        const int r0 = row_base + wm * 64 + i * 16 + g;
#pragma unroll
        for (int j = 0; j < 4; j++) {
            const int col = d0 + wn * 32 + j * 8 + 2 * t;
            float2 o0, o1;
            o0.x = acc[i][j][0] + bb[j].x;
            o0.y = acc[i][j][1] + bb[j].y;
            o1.x = acc[i][j][2] + bb[j].x;
            o1.y = acc[i][j][3] + bb[j].y;
            *reinterpret_cast<float2*>(out + (size_t)r0 * D_ + col) = o0;
            *reinterpret_cast<float2*>(out + (size_t)(r0 + 8) * D_ + col) = o1;
        }
    }
}

// ------------------------------------------------------------------ launch ---
extern "C" void kernel_launch(void* const* d_in, const int* in_sizes, int n_in,
                              void* d_out, int out_size) {
    const float* x     = (const float*)d_in[0];
    const float* w     = (const float*)d_in[1];
    const float* b     = (const float*)d_in[2];
    const float* gamma = (const float*)d_in[3];
    const float* beta  = (const float*)d_in[4];
    float* out = (float*)d_out;

    cudaFuncSetAttribute(ln_gemm_kernel, cudaFuncAttributeMaxDynamicSharedMemorySize, SMEM_DYN);

    ln_stats_kernel<<<ROWS, 256>>>(x);
    w_frag_kernel<<<dim3(NCHUNK, NB), 256>>>(w);
    ln_frag_kernel<<<dim3(NCHUNK, RB), 256>>>(x, gamma, beta);
    ln_gemm_kernel<<<dim3(NB, RB), 256, SMEM_DYN>>>(b, out);
}